// round 6
// baseline (speedup 1.0000x reference)
#include <cuda_runtime.h>
#include <cstdint>
#include <math.h>

// (B, L, H, E) = (4, 2048, 16, 64), qkv: (B, L, 3, H, E) fp32
#define BB 4
#define LL 2048
#define HH 16
#define EE 64

#define BQ 64        // Q rows per CTA (16 per warp x 4 warps)
#define BK 32        // K/V rows per tile (double buffered)
#define NTHREAD 128

#define SQ_STRIDE 68          // Q/P rows (round-3 verified)

// K' fragment-order layout: [nblk 0..3][lane 0..31][i 0..15 (+4 pad)]
//   i = 2*kk + half ; value = K[nblk*8 + (lane>>2)][kk*8 + (lane&3) + half*4]
#define KP_LANE_STRIDE 20
#define KP_NBLK_STRIDE (32 * KP_LANE_STRIDE)   // 640 floats
#define KP_BUF (4 * KP_NBLK_STRIDE)            // 2560 floats per buffer

// V' fragment-order layout: [eblk 0..7][lane 0..31][i 0..7 (+4 pad)]
//   i = 2*kk + half ; value = V[kk*8 + (lane&3) + half*4][eblk*8 + (lane>>2)]
#define VP_LANE_STRIDE 12
#define VP_NBLK_STRIDE (32 * VP_LANE_STRIDE)   // 384 floats
#define VP_BUF (8 * VP_NBLK_STRIDE)            // 3072 floats per buffer

#define NEG_INF (-1e30f)

__device__ __forceinline__ unsigned f2tf(float x) {
    unsigned r;
    asm("cvt.rna.tf32.f32 %0, %1;" : "=r"(r) : "f"(x));
    return r;
}
__device__ __forceinline__ float tf(float x) { return __uint_as_float(f2tf(x)); }

__device__ __forceinline__ void mma_tf32(float c[4], const unsigned a[4], unsigned b0, unsigned b1) {
    asm volatile(
        "mma.sync.aligned.m16n8k8.row.col.f32.tf32.tf32.f32 "
        "{%0,%1,%2,%3},{%4,%5,%6,%7},{%8,%9},{%0,%1,%2,%3};"
        : "+f"(c[0]), "+f"(c[1]), "+f"(c[2]), "+f"(c[3])
        : "r"(a[0]), "r"(a[1]), "r"(a[2]), "r"(a[3]), "r"(b0), "r"(b1));
}

// scatter one K float4 (token r, cols c..c+3) into fragment-order K'
__device__ __forceinline__ void commit_k(float* dKp, int r, int c, float4 v) {
    int n = r >> 3, g = r & 7;
    int i = ((c >> 3) << 1) + ((c >> 2) & 1);
    float* dst = dKp + n * KP_NBLK_STRIDE + (4 * g) * KP_LANE_STRIDE + i;
    dst[0]                  = tf(v.x);   // lane 4g+0
    dst[KP_LANE_STRIDE]     = tf(v.y);   // lane 4g+1
    dst[2 * KP_LANE_STRIDE] = tf(v.z);   // lane 4g+2
    dst[3 * KP_LANE_STRIDE] = tf(v.w);   // lane 4g+3
}

// scatter one V float4 (token r, e cols c..c+3) into fragment-order V'
__device__ __forceinline__ void commit_v(float* dVp, int r, int c, float4 v) {
    int n  = c >> 3;
    int g0 = c & 7;               // 0 or 4
    int tv = r & 3;
    int i  = ((r >> 3) << 1) + ((r >> 2) & 1);
    float* dst = dVp + n * VP_NBLK_STRIDE + (4 * g0 + tv) * VP_LANE_STRIDE + i;
    dst[0]                   = tf(v.x);  // lane 4*g0+tv
    dst[4 * VP_LANE_STRIDE]  = tf(v.y);  // lane 4*(g0+1)+tv
    dst[8 * VP_LANE_STRIDE]  = tf(v.z);
    dst[12 * VP_LANE_STRIDE] = tf(v.w);
}

__global__ __launch_bounds__(NTHREAD, 3)
void fa_tf32_kernel(const float* __restrict__ qkv, float* __restrict__ out) {
    extern __shared__ float smem[];
    float* sQ  = smem;                     // 64 x 68 (cols 0..31 reused as P)
    float* sKp = sQ + BQ * SQ_STRIDE;      // 2 x 2560
    float* sVp = sKp + 2 * KP_BUF;         // 2 x 3072

    const int tid  = threadIdx.x;
    const int w    = tid >> 5;
    const int lane = tid & 31;
    const int grp  = lane >> 2;
    const int tq   = lane & 3;

    const int qi = gridDim.x - 1 - blockIdx.x;   // heavy tiles first
    const int bh = blockIdx.y;
    const int b  = bh / HH;
    const int h  = bh % HH;
    const int q0 = qi * BQ;
    const int nkv = 2 * (qi + 1);

    const size_t HE  = (size_t)HH * EE;   // 1024
    const size_t ROW = 3 * HE;            // 3072

    // ---- Q tile: LDG -> *0.125 -> tf32 -> smem (row-major) ----
    // BQ=64 rows x 16 float4/row = 1024 slots -> 8 passes of 128 threads
    {
        const float* gq = qkv + ((size_t)(b * LL + q0) * 3) * HE + (size_t)h * EE;
        #pragma unroll
        for (int p = 0; p < 8; ++p) {
            int it = tid + p * NTHREAD;
            int r = it >> 4, c = (it & 15) << 2;
            float4 v = *(const float4*)(gq + (size_t)r * ROW + c);
            v.x = tf(v.x * 0.125f); v.y = tf(v.y * 0.125f);
            v.z = tf(v.z * 0.125f); v.w = tf(v.w * 0.125f);
            *(float4*)(sQ + r * SQ_STRIDE + c) = v;
        }
    }

    const float* gkv_base = qkv + ((size_t)b * LL * 3 + 1) * HE + (size_t)h * EE;

    // ---- KV tile 0 directly into buffer 0 (fragment-order); 512 slots = 4 passes ----
    {
        const float* gk = gkv_base;
        const float* gv = gk + HE;
        #pragma unroll
        for (int p = 0; p < 4; ++p) {
            int it = tid + p * NTHREAD;
            int r = it >> 4, c = (it & 15) << 2;
            commit_k(sKp, r, c, *(const float4*)(gk + (size_t)r * ROW + c));
        }
        #pragma unroll
        for (int p = 0; p < 4; ++p) {
            int it = tid + p * NTHREAD;
            int r = it >> 4, c = (it & 15) << 2;
            commit_v(sVp, r, c, *(const float4*)(gv + (size_t)r * ROW + c));
        }
    }
    __syncthreads();

    // ---- Q A-fragments (round-3 verified scalar reads) ----
    unsigned qa[8][4];
    {
        const float* r0 = sQ + (w * 16 + grp) * SQ_STRIDE;
        const float* r1 = r0 + 8 * SQ_STRIDE;
        #pragma unroll
        for (int k = 0; k < 8; ++k) {
            qa[k][0] = __float_as_uint(r0[k * 8 + tq]);
            qa[k][1] = __float_as_uint(r1[k * 8 + tq]);
            qa[k][2] = __float_as_uint(r0[k * 8 + tq + 4]);
            qa[k][3] = __float_as_uint(r1[k * 8 + tq + 4]);
        }
    }

    float o[8][4];
    #pragma unroll
    for (int n = 0; n < 8; ++n) { o[n][0] = 0.f; o[n][1] = 0.f; o[n][2] = 0.f; o[n][3] = 0.f; }
    float m0 = NEG_INF, m1 = NEG_INF;
    float l0 = 0.f, l1 = 0.f;

    for (int j = 0; j < nkv; ++j) {
        // ---- stage tile j+1 into registers (raw fp32) ----
        float4 ks[4], vsf[4];
        const bool have_next = (j + 1 < nkv);
        if (have_next) {
            const float* gk = gkv_base + (size_t)(j + 1) * BK * ROW;
            const float* gv = gk + HE;
            #pragma unroll
            for (int p = 0; p < 4; ++p) {
                int it = tid + p * NTHREAD;
                int r = it >> 4, c = (it & 15) << 2;
                ks[p]  = *(const float4*)(gk + (size_t)r * ROW + c);
                vsf[p] = *(const float4*)(gv + (size_t)r * ROW + c);
            }
        }

        const float* cKp = sKp + (j & 1) * KP_BUF;
        const float* cVp = sVp + (j & 1) * VP_BUF;

        // ---- S = Q K^T : 16x32 per warp, vectorized fragment loads ----
        float sc[4][4];
        #pragma unroll
        for (int n = 0; n < 4; ++n) { sc[n][0] = 0.f; sc[n][1] = 0.f; sc[n][2] = 0.f; sc[n][3] = 0.f; }

        #pragma unroll
        for (int n = 0; n < 4; ++n) {
            const float4* kn = (const float4*)(cKp + n * KP_NBLK_STRIDE + lane * KP_LANE_STRIDE);
            float4 x0 = kn[0], x1 = kn[1], x2 = kn[2], x3 = kn[3];
            mma_tf32(sc[n], qa[0], __float_as_uint(x0.x), __float_as_uint(x0.y));
            mma_tf32(sc[n], qa[1], __float_as_uint(x0.z), __float_as_uint(x0.w));
            mma_tf32(sc[n], qa[2], __float_as_uint(x1.x), __float_as_uint(x1.y));
            mma_tf32(sc[n], qa[3], __float_as_uint(x1.z), __float_as_uint(x1.w));
            mma_tf32(sc[n], qa[4], __float_as_uint(x2.x), __float_as_uint(x2.y));
            mma_tf32(sc[n], qa[5], __float_as_uint(x2.z), __float_as_uint(x2.w));
            mma_tf32(sc[n], qa[6], __float_as_uint(x3.x), __float_as_uint(x3.y));
            mma_tf32(sc[n], qa[7], __float_as_uint(x3.z), __float_as_uint(x3.w));
        }

        // ---- causal mask (only last two kv tiles can cross the diagonal) ----
        if (j >= nkv - 2) {
            const int kb  = j * BK;
            const int r0a = q0 + w * 16 + grp;
            const int r1a = r0a + 8;
            #pragma unroll
            for (int n = 0; n < 4; ++n) {
                int c0 = kb + n * 8 + tq * 2;
                if (c0 > r0a)     sc[n][0] = NEG_INF;
                if (c0 + 1 > r0a) sc[n][1] = NEG_INF;
                if (c0 > r1a)     sc[n][2] = NEG_INF;
                if (c0 + 1 > r1a) sc[n][3] = NEG_INF;
            }
        }

        // ---- online softmax ----
        float mx0 = NEG_INF, mx1 = NEG_INF;
        #pragma unroll
        for (int n = 0; n < 4; ++n) {
            mx0 = fmaxf(mx0, fmaxf(sc[n][0], sc[n][1]));
            mx1 = fmaxf(mx1, fmaxf(sc[n][2], sc[n][3]));
        }
        mx0 = fmaxf(mx0, __shfl_xor_sync(0xffffffffu, mx0, 1));
        mx0 = fmaxf(mx0, __shfl_xor_sync(0xffffffffu, mx0, 2));
        mx1 = fmaxf(mx1, __shfl_xor_sync(0xffffffffu, mx1, 1));
        mx1 = fmaxf(mx1, __shfl_xor_sync(0xffffffffu, mx1, 2));

        float mn0 = fmaxf(m0, mx0);
        float mn1 = fmaxf(m1, mx1);
        float a0 = __expf(m0 - mn0);
        float a1 = __expf(m1 - mn1);
        m0 = mn0; m1 = mn1;

        float s0 = 0.f, s1 = 0.f;
        #pragma unroll
        for (int n = 0; n < 4; ++n) {
            sc[n][0] = __expf(sc[n][0] - mn0); s0 += sc[n][0];
            sc[n][1] = __expf(sc[n][1] - mn0); s0 += sc[n][1];
            sc[n][2] = __expf(sc[n][2] - mn1); s1 += sc[n][2];
            sc[n][3] = __expf(sc[n][3] - mn1); s1 += sc[n][3];
        }
        s0 += __shfl_xor_sync(0xffffffffu, s0, 1);
        s0 += __shfl_xor_sync(0xffffffffu, s0, 2);
        s1 += __shfl_xor_sync(0xffffffffu, s1, 1);
        s1 += __shfl_xor_sync(0xffffffffu, s1, 2);
        l0 = l0 * a0 + s0;
        l1 = l1 * a1 + s1;

        #pragma unroll
        for (int n = 0; n < 8; ++n) {
            o[n][0] *= a0; o[n][1] *= a0;
            o[n][2] *= a1; o[n][3] *= a1;
        }

        // ---- P -> smem (warp-private rows of sQ, cols 0..31), tf32 ----
        {
            float* p0 = sQ + (w * 16 + grp) * SQ_STRIDE;
            float* p1 = p0 + 8 * SQ_STRIDE;
            #pragma unroll
            for (int n = 0; n < 4; ++n) {
                int c = n * 8 + tq * 2;
                *(float2*)(p0 + c) = make_float2(tf(sc[n][0]), tf(sc[n][1]));
                *(float2*)(p1 + c) = make_float2(tf(sc[n][2]), tf(sc[n][3]));
            }
        }
        __syncwarp();

        // ---- O += P V : P A-frags (round-3 scalar), V B-frags vectorized ----
        {
            unsigned aa[4][4];
            const float* p0 = sQ + (w * 16 + grp) * SQ_STRIDE;
            const float* p1 = p0 + 8 * SQ_STRIDE;
            #pragma unroll
            for (int k = 0; k < 4; ++k) {
                aa[k][0] = __float_as_uint(p0[k * 8 + tq]);
                aa[k][1] = __float_as_uint(p1[k * 8 + tq]);
                aa[k][2] = __float_as_uint(p0[k * 8 + tq + 4]);
                aa[k][3] = __float_as_uint(p1[k * 8 + tq + 4]);
            }
            #pragma unroll
            for (int n = 0; n < 8; ++n) {
                const float4* vn = (const float4*)(cVp + n * VP_NBLK_STRIDE + lane * VP_LANE_STRIDE);
                float4 y0 = vn[0], y1 = vn[1];
                mma_tf32(o[n], aa[0], __float_as_uint(y0.x), __float_as_uint(y0.y));
                mma_tf32(o[n], aa[1], __float_as_uint(y0.z), __float_as_uint(y0.w));
                mma_tf32(o[n], aa[2], __float_as_uint(y1.x), __float_as_uint(y1.y));
                mma_tf32(o[n], aa[3], __float_as_uint(y1.z), __float_as_uint(y1.w));
            }
        }
        __syncwarp();   // P reads done before next tile's P writes

        // ---- commit staged tile j+1 (convert + scatter to fragment order) ----
        if (have_next) {
            __syncthreads();   // all warps done reading buffer (j+1)&1 (iter j-1)
            float* dKp = sKp + ((j + 1) & 1) * KP_BUF;
            float* dVp = sVp + ((j + 1) & 1) * VP_BUF;
            #pragma unroll
            for (int p = 0; p < 4; ++p) {
                int it = tid + p * NTHREAD;
                int r = it >> 4, c = (it & 15) << 2;
                commit_k(dKp, r, c, ks[p]);
                commit_v(dVp, r, c, vsf[p]);
            }
            __syncthreads();   // commits visible before next iteration's compute
        }
    }

    // ---- epilogue: normalize and store ----
    {
        float inv0 = 1.0f / l0;
        float inv1 = 1.0f / l1;
        const int r0 = q0 + w * 16 + grp;
        const int r1 = r0 + 8;
        float* o0 = out + ((size_t)(b * LL + r0) * HH + h) * EE;
        float* o1 = out + ((size_t)(b * LL + r1) * HH + h) * EE;
        #pragma unroll
        for (int n = 0; n < 8; ++n) {
            int c = n * 8 + tq * 2;
            *(float2*)(o0 + c) = make_float2(o[n][0] * inv0, o[n][1] * inv0);
            *(float2*)(o1 + c) = make_float2(o[n][2] * inv1, o[n][3] * inv1);
        }
    }
}

extern "C" void kernel_launch(void* const* d_in, const int* in_sizes, int n_in,
                              void* d_out, int out_size) {
    const float* qkv = (const float*)d_in[0];
    float* out = (float*)d_out;

    const int smem_bytes = (BQ * SQ_STRIDE + 2 * KP_BUF + 2 * VP_BUF) * (int)sizeof(float);
    cudaFuncSetAttribute(fa_tf32_kernel, cudaFuncAttributeMaxDynamicSharedMemorySize, smem_bytes);

    dim3 grid(LL / BQ, BB * HH);   // (32, 64)
    fa_tf32_kernel<<<grid, NTHREAD, smem_bytes>>>(qkv, out);
}

// round 7
// speedup vs baseline: 1.7525x; 1.7525x over previous
#include <cuda_runtime.h>
#include <cstdint>
#include <math.h>

// (B, L, H, E) = (4, 2048, 16, 64), qkv: (B, L, 3, H, E) fp32
#define BB 4
#define LL 2048
#define HH 16
#define EE 64

#define BQ 64        // Q rows per CTA (16 per warp x 4 warps)
#define BK 32        // K/V rows per tile (double buffered)
#define NTHREAD 128

#define SQ_STRIDE 68   // Q/P rows (round-3 verified)
#define SV_STRIDE 72   // V rows, row-major (round-3 verified)

// K' fragment-order layout (round-6 verified correct AND conflict-free):
//   [nblk 0..3][lane 0..31][i 0..15 (+4 pad)]
//   i = 2*kk + half ; value = K[nblk*8 + (lane>>2)][kk*8 + (lane&3) + half*4]
#define KP_LANE_STRIDE 20
#define KP_NBLK_STRIDE (32 * KP_LANE_STRIDE)   // 640 floats
#define KP_BUF (4 * KP_NBLK_STRIDE)            // 2560 floats per buffer

#define NEG_INF (-1e30f)

__device__ __forceinline__ unsigned f2tf(float x) {
    unsigned r;
    asm("cvt.rna.tf32.f32 %0, %1;" : "=r"(r) : "f"(x));
    return r;
}
__device__ __forceinline__ float tf(float x) { return __uint_as_float(f2tf(x)); }

__device__ __forceinline__ void mma_tf32(float c[4], const unsigned a[4], unsigned b0, unsigned b1) {
    asm volatile(
        "mma.sync.aligned.m16n8k8.row.col.f32.tf32.tf32.f32 "
        "{%0,%1,%2,%3},{%4,%5,%6,%7},{%8,%9},{%0,%1,%2,%3};"
        : "+f"(c[0]), "+f"(c[1]), "+f"(c[2]), "+f"(c[3])
        : "r"(a[0]), "r"(a[1]), "r"(a[2]), "r"(a[3]), "r"(b0), "r"(b1));
}

// scatter one K float4 (token r, cols c..c+3) into fragment-order K' (tf32-rounded)
__device__ __forceinline__ void commit_k(float* dKp, int r, int c, float4 v) {
    int n = r >> 3, g = r & 7;
    int i = ((c >> 3) << 1) + ((c >> 2) & 1);
    float* dst = dKp + n * KP_NBLK_STRIDE + (4 * g) * KP_LANE_STRIDE + i;
    dst[0]                  = tf(v.x);   // lane 4g+0
    dst[KP_LANE_STRIDE]     = tf(v.y);   // lane 4g+1
    dst[2 * KP_LANE_STRIDE] = tf(v.z);   // lane 4g+2
    dst[3 * KP_LANE_STRIDE] = tf(v.w);   // lane 4g+3
}

__global__ __launch_bounds__(NTHREAD, 3)
void fa_tf32_kernel(const float* __restrict__ qkv, float* __restrict__ out) {
    extern __shared__ float smem[];
    float* sQ  = smem;                     // 64 x 68 (cols 0..31 reused as P)
    float* sKp = sQ + BQ * SQ_STRIDE;      // 2 x 2560 (fragment-order K')
    float* sV  = sKp + 2 * KP_BUF;         // 2 x 32 x 72 (row-major, tf32)

    const int tid  = threadIdx.x;
    const int w    = tid >> 5;
    const int lane = tid & 31;
    const int grp  = lane >> 2;
    const int tq   = lane & 3;

    const int qi = gridDim.x - 1 - blockIdx.x;   // heavy tiles first
    const int bh = blockIdx.y;
    const int b  = bh / HH;
    const int h  = bh % HH;
    const int q0 = qi * BQ;
    const int nkv = 2 * (qi + 1);

    const size_t HE  = (size_t)HH * EE;   // 1024
    const size_t ROW = 3 * HE;            // 3072

    // ---- Q tile: LDG -> *0.125 -> tf32 -> smem (row-major); 1024 slots = 8 passes ----
    {
        const float* gq = qkv + ((size_t)(b * LL + q0) * 3) * HE + (size_t)h * EE;
        #pragma unroll
        for (int p = 0; p < 8; ++p) {
            int it = tid + p * NTHREAD;
            int r = it >> 4, c = (it & 15) << 2;
            float4 v = *(const float4*)(gq + (size_t)r * ROW + c);
            v.x = tf(v.x * 0.125f); v.y = tf(v.y * 0.125f);
            v.z = tf(v.z * 0.125f); v.w = tf(v.w * 0.125f);
            *(float4*)(sQ + r * SQ_STRIDE + c) = v;
        }
    }

    const float* gkv_base = qkv + ((size_t)b * LL * 3 + 1) * HE + (size_t)h * EE;

    // ---- KV tile 0 into buffer 0; 512 slots = 4 passes each ----
    {
        const float* gk = gkv_base;
        const float* gv = gk + HE;
        #pragma unroll
        for (int p = 0; p < 4; ++p) {
            int it = tid + p * NTHREAD;
            int r = it >> 4, c = (it & 15) << 2;
            commit_k(sKp, r, c, *(const float4*)(gk + (size_t)r * ROW + c));
        }
        #pragma unroll
        for (int p = 0; p < 4; ++p) {
            int it = tid + p * NTHREAD;
            int r = it >> 4, c = (it & 15) << 2;
            float4 v = *(const float4*)(gv + (size_t)r * ROW + c);
            v.x = tf(v.x); v.y = tf(v.y); v.z = tf(v.z); v.w = tf(v.w);
            *(float4*)(sV + r * SV_STRIDE + c) = v;
        }
    }
    __syncthreads();

    // ---- Q A-fragments (round-3 verified scalar reads; values already tf32) ----
    unsigned qa[8][4];
    {
        const float* r0 = sQ + (w * 16 + grp) * SQ_STRIDE;
        const float* r1 = r0 + 8 * SQ_STRIDE;
        #pragma unroll
        for (int k = 0; k < 8; ++k) {
            qa[k][0] = __float_as_uint(r0[k * 8 + tq]);
            qa[k][1] = __float_as_uint(r1[k * 8 + tq]);
            qa[k][2] = __float_as_uint(r0[k * 8 + tq + 4]);
            qa[k][3] = __float_as_uint(r1[k * 8 + tq + 4]);
        }
    }

    float o[8][4];
    #pragma unroll
    for (int n = 0; n < 8; ++n) { o[n][0] = 0.f; o[n][1] = 0.f; o[n][2] = 0.f; o[n][3] = 0.f; }
    float m0 = NEG_INF, m1 = NEG_INF;
    float l0 = 0.f, l1 = 0.f;

    for (int j = 0; j < nkv; ++j) {
        // ---- stage tile j+1 into registers (raw fp32) ----
        float4 ks[4], vsf[4];
        const bool have_next = (j + 1 < nkv);
        if (have_next) {
            const float* gk = gkv_base + (size_t)(j + 1) * BK * ROW;
            const float* gv = gk + HE;
            #pragma unroll
            for (int p = 0; p < 4; ++p) {
                int it = tid + p * NTHREAD;
                int r = it >> 4, c = (it & 15) << 2;
                ks[p]  = *(const float4*)(gk + (size_t)r * ROW + c);
                vsf[p] = *(const float4*)(gv + (size_t)r * ROW + c);
            }
        }

        const float* cKp = sKp + (j & 1) * KP_BUF;
        const float* cV  = sV  + (j & 1) * (BK * SV_STRIDE);

        // ---- S = Q K^T : 16x32 per warp, vectorized K' fragment loads ----
        float sc[4][4];
        #pragma unroll
        for (int n = 0; n < 4; ++n) { sc[n][0] = 0.f; sc[n][1] = 0.f; sc[n][2] = 0.f; sc[n][3] = 0.f; }

        #pragma unroll
        for (int n = 0; n < 4; ++n) {
            const float4* kn = (const float4*)(cKp + n * KP_NBLK_STRIDE + lane * KP_LANE_STRIDE);
            float4 x0 = kn[0], x1 = kn[1], x2 = kn[2], x3 = kn[3];
            mma_tf32(sc[n], qa[0], __float_as_uint(x0.x), __float_as_uint(x0.y));
            mma_tf32(sc[n], qa[1], __float_as_uint(x0.z), __float_as_uint(x0.w));
            mma_tf32(sc[n], qa[2], __float_as_uint(x1.x), __float_as_uint(x1.y));
            mma_tf32(sc[n], qa[3], __float_as_uint(x1.z), __float_as_uint(x1.w));
            mma_tf32(sc[n], qa[4], __float_as_uint(x2.x), __float_as_uint(x2.y));
            mma_tf32(sc[n], qa[5], __float_as_uint(x2.z), __float_as_uint(x2.w));
            mma_tf32(sc[n], qa[6], __float_as_uint(x3.x), __float_as_uint(x3.y));
            mma_tf32(sc[n], qa[7], __float_as_uint(x3.z), __float_as_uint(x3.w));
        }

        // ---- causal mask (only last two kv tiles can cross the diagonal) ----
        if (j >= nkv - 2) {
            const int kb  = j * BK;
            const int r0a = q0 + w * 16 + grp;
            const int r1a = r0a + 8;
            #pragma unroll
            for (int n = 0; n < 4; ++n) {
                int c0 = kb + n * 8 + tq * 2;
                if (c0 > r0a)     sc[n][0] = NEG_INF;
                if (c0 + 1 > r0a) sc[n][1] = NEG_INF;
                if (c0 > r1a)     sc[n][2] = NEG_INF;
                if (c0 + 1 > r1a) sc[n][3] = NEG_INF;
            }
        }

        // ---- online softmax ----
        float mx0 = NEG_INF, mx1 = NEG_INF;
        #pragma unroll
        for (int n = 0; n < 4; ++n) {
            mx0 = fmaxf(mx0, fmaxf(sc[n][0], sc[n][1]));
            mx1 = fmaxf(mx1, fmaxf(sc[n][2], sc[n][3]));
        }
        mx0 = fmaxf(mx0, __shfl_xor_sync(0xffffffffu, mx0, 1));
        mx0 = fmaxf(mx0, __shfl_xor_sync(0xffffffffu, mx0, 2));
        mx1 = fmaxf(mx1, __shfl_xor_sync(0xffffffffu, mx1, 1));
        mx1 = fmaxf(mx1, __shfl_xor_sync(0xffffffffu, mx1, 2));

        float mn0 = fmaxf(m0, mx0);
        float mn1 = fmaxf(m1, mx1);
        float a0 = __expf(m0 - mn0);
        float a1 = __expf(m1 - mn1);
        m0 = mn0; m1 = mn1;

        float s0 = 0.f, s1 = 0.f;
        #pragma unroll
        for (int n = 0; n < 4; ++n) {
            sc[n][0] = __expf(sc[n][0] - mn0); s0 += sc[n][0];
            sc[n][1] = __expf(sc[n][1] - mn0); s0 += sc[n][1];
            sc[n][2] = __expf(sc[n][2] - mn1); s1 += sc[n][2];
            sc[n][3] = __expf(sc[n][3] - mn1); s1 += sc[n][3];
        }
        s0 += __shfl_xor_sync(0xffffffffu, s0, 1);
        s0 += __shfl_xor_sync(0xffffffffu, s0, 2);
        s1 += __shfl_xor_sync(0xffffffffu, s1, 1);
        s1 += __shfl_xor_sync(0xffffffffu, s1, 2);
        l0 = l0 * a0 + s0;
        l1 = l1 * a1 + s1;

        #pragma unroll
        for (int n = 0; n < 8; ++n) {
            o[n][0] *= a0; o[n][1] *= a0;
            o[n][2] *= a1; o[n][3] *= a1;
        }

        // ---- P -> smem (warp-private rows of sQ, cols 0..31), tf32 ----
        {
            float* p0 = sQ + (w * 16 + grp) * SQ_STRIDE;
            float* p1 = p0 + 8 * SQ_STRIDE;
            #pragma unroll
            for (int n = 0; n < 4; ++n) {
                int c = n * 8 + tq * 2;
                *(float2*)(p0 + c) = make_float2(tf(sc[n][0]), tf(sc[n][1]));
                *(float2*)(p1 + c) = make_float2(tf(sc[n][2]), tf(sc[n][3]));
            }
        }
        __syncwarp();

        // ---- O += P V : round-3 layout, values already tf32 (no CVT) ----
        {
            const float* p0 = sQ + (w * 16 + grp) * SQ_STRIDE;
            const float* p1 = p0 + 8 * SQ_STRIDE;
            #pragma unroll
            for (int k = 0; k < 4; ++k) {
                unsigned aa[4];
                aa[0] = __float_as_uint(p0[k * 8 + tq]);
                aa[1] = __float_as_uint(p1[k * 8 + tq]);
                aa[2] = __float_as_uint(p0[k * 8 + tq + 4]);
                aa[3] = __float_as_uint(p1[k * 8 + tq + 4]);
                const float* v0 = cV + (k * 8 + tq) * SV_STRIDE;
                const float* v1 = cV + (k * 8 + tq + 4) * SV_STRIDE;
                #pragma unroll
                for (int n = 0; n < 8; ++n) {
                    unsigned b0 = __float_as_uint(v0[n * 8 + grp]);
                    unsigned b1 = __float_as_uint(v1[n * 8 + grp]);
                    mma_tf32(o[n], aa, b0, b1);
                }
            }
        }
        __syncwarp();   // P reads done before next tile's P writes

        // ---- commit staged tile j+1 ----
        if (have_next) {
            __syncthreads();   // all warps done reading buffer (j+1)&1 (iter j-1)
            float* dKp = sKp + ((j + 1) & 1) * KP_BUF;
            float* dV  = sV  + ((j + 1) & 1) * (BK * SV_STRIDE);
            #pragma unroll
            for (int p = 0; p < 4; ++p) {
                int it = tid + p * NTHREAD;
                int r = it >> 4, c = (it & 15) << 2;
                commit_k(dKp, r, c, ks[p]);
                float4 v = vsf[p];
                v.x = tf(v.x); v.y = tf(v.y); v.z = tf(v.z); v.w = tf(v.w);
                *(float4*)(dV + r * SV_STRIDE + c) = v;
            }
            __syncthreads();   // commits visible before next iteration's compute
        }
    }

    // ---- epilogue: normalize and store ----
    {
        float inv0 = 1.0f / l0;
        float inv1 = 1.0f / l1;
        const int r0 = q0 + w * 16 + grp;
        const int r1 = r0 + 8;
        float* o0 = out + ((size_t)(b * LL + r0) * HH + h) * EE;
        float* o1 = out + ((size_t)(b * LL + r1) * HH + h) * EE;
        #pragma unroll
        for (int n = 0; n < 8; ++n) {
            int c = n * 8 + tq * 2;
            *(float2*)(o0 + c) = make_float2(o[n][0] * inv0, o[n][1] * inv0);
            *(float2*)(o1 + c) = make_float2(o[n][2] * inv1, o[n][3] * inv1);
        }
    }
}

extern "C" void kernel_launch(void* const* d_in, const int* in_sizes, int n_in,
                              void* d_out, int out_size) {
    const float* qkv = (const float*)d_in[0];
    float* out = (float*)d_out;

    const int smem_bytes = (BQ * SQ_STRIDE + 2 * KP_BUF + 2 * BK * SV_STRIDE) * (int)sizeof(float);
    cudaFuncSetAttribute(fa_tf32_kernel, cudaFuncAttributeMaxDynamicSharedMemorySize, smem_bytes);

    dim3 grid(LL / BQ, BB * HH);   // (32, 64)
    fa_tf32_kernel<<<grid, NTHREAD, smem_bytes>>>(qkv, out);
}